// round 13
// baseline (speedup 1.0000x reference)
#include <cuda_runtime.h>
#include <cuda_fp16.h>
#include <math_constants.h>
#include <cstdint>

#define N      8192
#define D      128
#define THR    1e-4f
#define SPLIT  16
#define BK     64
#define JR     (N / SPLIT)          // 512 j per unit
#define NT     (JR / BK)            // 8 K-iterations per unit
#define MB     64                   // i-rows per unit
#define NIB    (N / MB)             // 128 i-blocks
#define NUNITS (NIB * SPLIT)        // 2048 work units
#define NCTA   444                  // 148 SMs x 3
#define SROWS  8

// ---------------- scratch (static device globals; no allocation) ------------
__device__ float    g_h[N * D];                    // 4 MB fp32 h (residual)
__device__ float    g_src[N], g_Bz[N], g_Cz[N];
__device__ float4   g_rowc[N];                     // {eaF, ebF, T3, -}
__device__ unsigned g_mask[(size_t)N * N / 32];    // 8 MB adjacency bits
__device__ __align__(16) __half g_hh[N * D];       // 2 MB h (fp16)
__device__ float    g_part[SPLIT][N * D];          // 64 MB split-K partials
__device__ unsigned g_ctr;                         // work-steal counter

// smem tile geometry (16-bit pitches; odd 16B-granule counts -> LDSM conflict-free)
#define APITCH 72     // 64 K-cols padded 64->72 (144 B = 9 granules)
#define BPITCH 136    // 128 cols padded ->136 (272 B = 17 granules)
#define A_BYTES (MB * APITCH * 2)                  // 9216
#define B_BYTES (BK * BPITCH * 2)                  // 17408
#define BUF_BYTES (A_BYTES + B_BYTES)              // 26624
#define SM_TAB    (2 * BUF_BYTES)                  // 53248
#define SMEM_DYN  (SM_TAB + 2 * JR * 4)            // 57344 -> 3 CTAs/SM

// ---------------- PTX helpers -----------------------------------------------
__device__ __forceinline__ uint32_t smem_u32(const void* p) {
    uint32_t a;
    asm("{ .reg .u64 t; cvta.to.shared.u64 t, %1; cvt.u32.u64 %0, t; }"
        : "=r"(a) : "l"(p));
    return a;
}
__device__ __forceinline__ void cpa16(uint32_t dst, const void* src) {
    asm volatile("cp.async.cg.shared.global [%0], [%1], 16;"
                 :: "r"(dst), "l"(src) : "memory");
}
#define CPA_COMMIT() asm volatile("cp.async.commit_group;" ::: "memory")
#define CPA_WAIT0()  asm volatile("cp.async.wait_group 0;" ::: "memory")

__device__ __forceinline__ void ldsm4(uint32_t* r, uint32_t addr) {
    asm volatile("ldmatrix.sync.aligned.m8n8.x4.shared.b16 {%0,%1,%2,%3}, [%4];"
                 : "=r"(r[0]), "=r"(r[1]), "=r"(r[2]), "=r"(r[3]) : "r"(addr));
}
__device__ __forceinline__ void ldsm4t(uint32_t* r, uint32_t addr) {
    asm volatile("ldmatrix.sync.aligned.m8n8.x4.trans.shared.b16 {%0,%1,%2,%3}, [%4];"
                 : "=r"(r[0]), "=r"(r[1]), "=r"(r[2]), "=r"(r[3]) : "r"(addr));
}
__device__ __forceinline__ void mma16816(float* c, const uint32_t* a,
                                         const uint32_t* b) {
    asm volatile("mma.sync.aligned.m16n8k16.row.col.f32.f16.f16.f32 "
                 "{%0,%1,%2,%3}, {%4,%5,%6,%7}, {%8,%9}, {%0,%1,%2,%3};"
                 : "+f"(c[0]), "+f"(c[1]), "+f"(c[2]), "+f"(c[3])
                 : "r"(a[0]), "r"(a[1]), "r"(a[2]), "r"(a[3]),
                   "r"(b[0]), "r"(b[1]));
}

// ---------------- K1: h = X @ W + per-node scalars + fp16 -------------------
__global__ void k_h(const float* __restrict__ x,
                    const float* __restrict__ W,
                    const float* __restrict__ a) {
    int i = blockIdx.x;
    int k = threadIdx.x;

    if (i == 0 && k == 0) g_ctr = 0;

    __shared__ float xs[D];
    __shared__ float red[D];
    __shared__ float res[3];

    xs[k] = x[i * D + k];
    __syncthreads();

    float acc = 0.f;
#pragma unroll 16
    for (int c = 0; c < D; ++c)
        acc = fmaf(xs[c], W[c * D + k], acc);

    g_h[i * D + k]  = acc;
    g_hh[i * D + k] = __float2half_rn(acc);

    float vals[3] = {acc, acc * a[k], acc * a[D + k]};
#pragma unroll
    for (int v = 0; v < 3; ++v) {
        red[k] = vals[v];
        __syncthreads();
        for (int st = 64; st > 0; st >>= 1) {
            if (k < st) red[k] += red[k + st];
            __syncthreads();
        }
        if (k == 0) res[v] = red[0];
        __syncthreads();
    }
    if (k == 0) {
        float rs = res[0], s = res[1], d = res[2];
        bool  nz = (rs != 0.0f);
        g_src[i] = s;
        g_Bz[i]  = nz ? __expf(d)        : 0.f;
        g_Cz[i]  = nz ? __expf(0.2f * d) : 0.f;
    }
}

// ---------------- K2: softmax stats + bitmask (MLP=4) -----------------------
__global__ void k_stats(const int* __restrict__ adj) {
    int row  = blockIdx.x * SROWS + (threadIdx.x >> 5);
    int lane = threadIdx.x & 31;

    float src = g_src[row];
    float ea  = __expf(src);
    float eb  = __expf(0.2f * src);

    float s = 0.f, vm = 0.f;
    int   cnt = 0;
    const int4* arow = (const int4*)(adj + (size_t)row * N);
    unsigned* mrow = g_mask + (size_t)row * (N / 32);

    for (int blk4 = 0; blk4 < N / 512; ++blk4) {
        int4 av[4];
#pragma unroll
        for (int q = 0; q < 4; ++q)
            av[q] = arow[blk4 * 128 + q * 32 + lane];
#pragma unroll
        for (int q = 0; q < 4; ++q) {
            int blk = blk4 * 4 + q;
            int j0  = blk * 128 + lane * 4;
            float4 bz = __ldg((const float4*)(g_Bz + j0));
            float4 cz = __ldg((const float4*)(g_Cz + j0));

            unsigned nib = (av[q].x > 0) | ((av[q].y > 0) << 1) |
                           ((av[q].z > 0) << 2) | ((av[q].w > 0) << 3);
            unsigned v = nib;
            v |= __shfl_down_sync(0xffffffffu, v, 1) << 4;
            v |= __shfl_down_sync(0xffffffffu, v, 2) << 8;
            v |= __shfl_down_sync(0xffffffffu, v, 4) << 16;
            if ((lane & 7) == 0)
                mrow[blk * 4 + (lane >> 3)] = v;

            float ba[4] = {bz.x, bz.y, bz.z, bz.w};
            float ca[4] = {cz.x, cz.y, cz.z, cz.w};
#pragma unroll
            for (int u = 0; u < 4; ++u) {
                float vv  = fmaxf(ea * ba[u], eb * ca[u]);
                bool  bit = (nib >> u) & 1u;
                float val = bit ? vv : 0.f;
                s  += val;
                vm  = fmaxf(vm, val);
                cnt += (bit && vv > 0.f) ? 1 : 0;
            }
        }
    }
#pragma unroll
    for (int o = 16; o > 0; o >>= 1) {
        s   += __shfl_xor_sync(0xffffffffu, s, o);
        vm   = fmaxf(vm, __shfl_xor_sync(0xffffffffu, vm, o));
        cnt += __shfl_xor_sync(0xffffffffu, cnt, o);
    }
    if (lane == 0) {
        bool active = (vm > THR * s);
        float eaF = 0.f, ebF = 0.f, T3 = CUDART_INF_F;
        if (active) {
            float F = (float)cnt / s;
            eaF = ea * F;
            ebF = eb * F;
            T3  = THR * (float)cnt;
        }
        g_rowc[row] = make_float4(eaF, ebF, T3, 0.f);
    }
}

// ---------------- K3: persistent MMA kernel (fp16 1-pass, BK=64) ------------
__global__ void __launch_bounds__(256, 3) k_agg() {
    extern __shared__ __align__(16) char sm[];
    __shared__ unsigned s_u;
    uint32_t smb = smem_u32(sm);

    int tid  = threadIdx.x;
    int lane = tid & 31;
    int wid  = tid >> 5;

    float* s_bz = (float*)(sm + SM_TAB);
    float* s_cz = s_bz + JR;

    int gi   = tid >> 2;          // gen row within i-block (0..63)
    int j16  = (tid & 3) << 4;    // gen 16-j slice within BK=64
    int wsel = j16 >> 5;          // which 32-bit mask word (0/1)
    int jsh  = j16 & 31;          // shift within word (0/16)
    int wm   = (wid & 1) * 32;    // mma warp tile: 2 x 4 grid of 32x32
    int wn   = (wid >> 1) * 32;

    while (true) {
        if (tid == 0) s_u = atomicAdd(&g_ctr, 1u);
        __syncthreads();
        unsigned u = s_u;
        if (u >= NUNITS) break;

        int split  = u >> 7;
        int iblk   = u & 127;
        int ib     = iblk * MB;
        int jstart = split * JR;

        float4 rc = g_rowc[ib + gi];
        const unsigned* mrow =
            g_mask + (size_t)(ib + gi) * (N / 32) + (jstart >> 5);

        float acc[2][4][4];
#pragma unroll
        for (int mf = 0; mf < 2; ++mf)
#pragma unroll
            for (int nf = 0; nf < 4; ++nf)
#pragma unroll
                for (int q = 0; q < 4; ++q) acc[mf][nf][q] = 0.f;

        auto loadB = [&](int t) {
            int b  = t & 1;
            int jb = jstart + t * BK;
            uint32_t Bh = smb + b * BUF_BYTES + A_BYTES;
#pragma unroll
            for (int q = 0; q < 4; ++q) {
                int idx = tid + q * 256;
                int r = idx >> 4, g = idx & 15;
                uint32_t doff = (uint32_t)(r * BPITCH + g * 8) * 2;
                cpa16(Bh + doff, g_hh + (size_t)(jb + r) * D + g * 8);
            }
            CPA_COMMIT();
        };

        auto gen_store = [&](int t, unsigned mw_word) {
            int b = t & 1;
            char* Ah = sm + b * BUF_BYTES;
            unsigned mw = mw_word >> jsh;
            int lj = t * BK + j16;
            const float4* tb = (const float4*)(s_bz + lj);
            const float4* tc = (const float4*)(s_cz + lj);
            uint32_t* a32 = (uint32_t*)Ah + gi * (APITCH / 2) + (j16 >> 1);
#pragma unroll
            for (int e = 0; e < 4; ++e) {
                float4 bz = tb[e];
                float4 cz = tc[e];
                float ba[4] = {bz.x, bz.y, bz.z, bz.w};
                float ca[4] = {cz.x, cz.y, cz.z, cz.w};
                float w[4];
#pragma unroll
                for (int k = 0; k < 4; ++k) {
                    float v  = fmaxf(rc.x * ba[k], rc.y * ca[k]);
                    bool  ok = (v >= rc.z) && ((mw >> (e * 4 + k)) & 1u);
                    w[k] = ok ? v : 0.f;
                }
                uint32_t p0, p1;
                asm("cvt.rn.f16x2.f32 %0, %1, %2;" : "=r"(p0) : "f"(w[1]), "f"(w[0]));
                asm("cvt.rn.f16x2.f32 %0, %1, %2;" : "=r"(p1) : "f"(w[3]), "f"(w[2]));
                *(uint2*)&a32[e * 2] = make_uint2(p0, p1);
            }
        };

        auto domma = [&](int t) {
            int b = t & 1;
            uint32_t Ah = smb + b * BUF_BYTES;
            uint32_t Bh = Ah + A_BYTES;
#pragma unroll
            for (int ks = 0; ks < 4; ++ks) {
                int k0 = ks * 16;
                uint32_t af[2][4];
#pragma unroll
                for (int mf = 0; mf < 2; ++mf) {
                    uint32_t row = wm + mf * 16 + (lane & 15);
                    uint32_t off = row * (APITCH * 2) + (k0 + ((lane >> 4) << 3)) * 2;
                    ldsm4(af[mf], Ah + off);
                }
#pragma unroll
                for (int nf2 = 0; nf2 < 2; ++nf2) {
                    int n0 = wn + nf2 * 16;
                    uint32_t r = k0 + (lane & 7) + ((lane >> 3) & 1) * 8;
                    uint32_t c = n0 + ((lane >> 4) << 3);
                    uint32_t off = r * (BPITCH * 2) + c * 2;
                    uint32_t bh[4];
                    ldsm4t(bh, Bh + off);
#pragma unroll
                    for (int mf = 0; mf < 2; ++mf) {
                        mma16816(acc[mf][nf2 * 2],     af[mf], bh);
                        mma16816(acc[mf][nf2 * 2 + 1], af[mf], bh + 2);
                    }
                }
            }
        };

        // ---- unit prologue ---------------------------------------------------
        loadB(0);
        if (tid < 128)
            ((float4*)s_bz)[tid] = __ldg((const float4*)(g_Bz + jstart) + tid);
        else
            ((float4*)s_cz)[tid - 128] =
                __ldg((const float4*)(g_Cz + jstart) + (tid - 128));
        __syncthreads();
        gen_store(0, __ldg(&mrow[wsel]));

        // ---- pipeline --------------------------------------------------------
        for (int t = 0; t < NT; ++t) {
            CPA_WAIT0();
            __syncthreads();
            unsigned mwn = 0;
            if (t + 1 < NT) {
                mwn = __ldg(&mrow[(t + 1) * 2 + wsel]);
                loadB(t + 1);
            }
            domma(t);
            if (t + 1 < NT) gen_store(t + 1, mwn);
        }

        // ---- epilogue: write split partial -----------------------------------
        int r0    = ib + wm + (lane >> 2);
        int cbase = wn + (lane & 3) * 2;
#pragma unroll
        for (int mf = 0; mf < 2; ++mf)
#pragma unroll
            for (int nf = 0; nf < 4; ++nf) {
                int row = r0 + mf * 16;
                int col = cbase + nf * 8;
                float* p = &g_part[split][(size_t)row * D + col];
                *(float2*)p           = make_float2(acc[mf][nf][0], acc[mf][nf][1]);
                *(float2*)(p + 8 * D) = make_float2(acc[mf][nf][2], acc[mf][nf][3]);
            }
    }
}

// ---------------- K4: combine partials + residual + ELU ---------------------
__global__ void k_out(float* __restrict__ out) {
    int g = blockIdx.x * blockDim.x + threadIdx.x;
    float4 v = ((const float4*)g_h)[g];
#pragma unroll
    for (int s = 0; s < SPLIT; ++s) {
        float4 p = __ldg((const float4*)g_part[s] + g);
        v.x += p.x; v.y += p.y; v.z += p.z; v.w += p.w;
    }
    float4 o;
    o.x = (v.x > 0.f) ? v.x : expm1f(v.x);
    o.y = (v.y > 0.f) ? v.y : expm1f(v.y);
    o.z = (v.z > 0.f) ? v.z : expm1f(v.z);
    o.w = (v.w > 0.f) ? v.w : expm1f(v.w);
    ((float4*)out)[g] = o;
}

// ---------------- launch ----------------------------------------------------
extern "C" void kernel_launch(void* const* d_in, const int* in_sizes, int n_in,
                              void* d_out, int out_size) {
    (void)in_sizes; (void)n_in; (void)out_size;
    const float* x   = (const float*)d_in[0];
    const float* W   = (const float*)d_in[1];
    const float* a   = (const float*)d_in[2];
    const int*   adj = (const int*)d_in[3];
    float*       out = (float*)d_out;

    cudaFuncSetAttribute(k_agg, cudaFuncAttributeMaxDynamicSharedMemorySize, SMEM_DYN);

    k_h    <<<N, 128>>>(x, W, a);
    k_stats<<<N / SROWS, 256>>>(adj);
    k_agg  <<<NCTA, 256, SMEM_DYN>>>();
    k_out  <<<(N * D) / 1024, 256>>>(out);
}

// round 14
// speedup vs baseline: 1.0189x; 1.0189x over previous
#include <cuda_runtime.h>
#include <cuda_fp16.h>
#include <math_constants.h>
#include <cstdint>

#define N      8192
#define D      128
#define THR    1e-4f
#define SPLIT  16
#define BK     32
#define JR     (N / SPLIT)          // 512 j per unit
#define NT     (JR / BK)            // 16 K-iterations per unit
#define MB     64                   // i-rows per unit
#define NIB    (N / MB)             // 128 i-blocks
#define NUNITS (NIB * SPLIT)        // 2048 work units
#define NCTA   296                  // 148 SMs x 2 (units/CTA = 6.92, tail ~1%)
#define SROWS  8

// ---------------- scratch (static device globals; no allocation) ------------
__device__ float    g_h[N * D];                    // 4 MB fp32 h (residual)
__device__ float    g_src[N], g_Bz[N], g_Cz[N];
__device__ float4   g_rowc[N];                     // {eaF, ebF, T3, -}
__device__ unsigned g_mask[(size_t)N * N / 32];    // 8 MB adjacency bits
__device__ __align__(16) __half g_hh[N * D];       // 2 MB h (fp16)
__device__ float    g_part[SPLIT][N * D];          // 64 MB split-K partials
__device__ unsigned g_ctr;                         // work-steal counter

// smem tile geometry (16-bit pitches; odd 16B-granule counts -> LDSM conflict-free)
#define APITCH 40
#define BPITCH 136
#define A_BYTES (MB * APITCH * 2)                  // 5120
#define B_BYTES (BK * BPITCH * 2)                  // 8704
#define BUF_BYTES (A_BYTES + B_BYTES)              // 13824
#define SM_TAB    (2 * BUF_BYTES)                  // 27648
#define SMEM_DYN  (SM_TAB + 2 * JR * 4)            // 31744

// ---------------- PTX helpers -----------------------------------------------
__device__ __forceinline__ uint32_t smem_u32(const void* p) {
    uint32_t a;
    asm("{ .reg .u64 t; cvta.to.shared.u64 t, %1; cvt.u32.u64 %0, t; }"
        : "=r"(a) : "l"(p));
    return a;
}
__device__ __forceinline__ void cpa16(uint32_t dst, const void* src) {
    asm volatile("cp.async.cg.shared.global [%0], [%1], 16;"
                 :: "r"(dst), "l"(src) : "memory");
}
#define CPA_COMMIT() asm volatile("cp.async.commit_group;" ::: "memory")
#define CPA_WAIT0()  asm volatile("cp.async.wait_group 0;" ::: "memory")

__device__ __forceinline__ void ldsm4(uint32_t* r, uint32_t addr) {
    asm volatile("ldmatrix.sync.aligned.m8n8.x4.shared.b16 {%0,%1,%2,%3}, [%4];"
                 : "=r"(r[0]), "=r"(r[1]), "=r"(r[2]), "=r"(r[3]) : "r"(addr));
}
__device__ __forceinline__ void ldsm4t(uint32_t* r, uint32_t addr) {
    asm volatile("ldmatrix.sync.aligned.m8n8.x4.trans.shared.b16 {%0,%1,%2,%3}, [%4];"
                 : "=r"(r[0]), "=r"(r[1]), "=r"(r[2]), "=r"(r[3]) : "r"(addr));
}
__device__ __forceinline__ void mma16816(float* c, const uint32_t* a,
                                         const uint32_t* b) {
    asm volatile("mma.sync.aligned.m16n8k16.row.col.f32.f16.f16.f32 "
                 "{%0,%1,%2,%3}, {%4,%5,%6,%7}, {%8,%9}, {%0,%1,%2,%3};"
                 : "+f"(c[0]), "+f"(c[1]), "+f"(c[2]), "+f"(c[3])
                 : "r"(a[0]), "r"(a[1]), "r"(a[2]), "r"(a[3]),
                   "r"(b[0]), "r"(b[1]));
}

// ---------------- K1: h = X @ W + per-node scalars + fp16 -------------------
__global__ void k_h(const float* __restrict__ x,
                    const float* __restrict__ W,
                    const float* __restrict__ a) {
    int i = blockIdx.x;
    int k = threadIdx.x;

    if (i == 0 && k == 0) g_ctr = 0;

    __shared__ float xs[D];
    __shared__ float red[D];
    __shared__ float res[3];

    xs[k] = x[i * D + k];
    __syncthreads();

    float acc = 0.f;
#pragma unroll 16
    for (int c = 0; c < D; ++c)
        acc = fmaf(xs[c], W[c * D + k], acc);

    g_h[i * D + k]  = acc;
    g_hh[i * D + k] = __float2half_rn(acc);

    float vals[3] = {acc, acc * a[k], acc * a[D + k]};
#pragma unroll
    for (int v = 0; v < 3; ++v) {
        red[k] = vals[v];
        __syncthreads();
        for (int st = 64; st > 0; st >>= 1) {
            if (k < st) red[k] += red[k + st];
            __syncthreads();
        }
        if (k == 0) res[v] = red[0];
        __syncthreads();
    }
    if (k == 0) {
        float rs = res[0], s = res[1], d = res[2];
        bool  nz = (rs != 0.0f);
        g_src[i] = s;
        g_Bz[i]  = nz ? __expf(d)        : 0.f;
        g_Cz[i]  = nz ? __expf(0.2f * d) : 0.f;
    }
}

// ---------------- K2: softmax stats + bitmask (MLP=4) -----------------------
__global__ void k_stats(const int* __restrict__ adj) {
    int row  = blockIdx.x * SROWS + (threadIdx.x >> 5);
    int lane = threadIdx.x & 31;

    float src = g_src[row];
    float ea  = __expf(src);
    float eb  = __expf(0.2f * src);

    float s = 0.f, vm = 0.f;
    int   cnt = 0;
    const int4* arow = (const int4*)(adj + (size_t)row * N);
    unsigned* mrow = g_mask + (size_t)row * (N / 32);

    for (int blk4 = 0; blk4 < N / 512; ++blk4) {
        int4 av[4];
#pragma unroll
        for (int q = 0; q < 4; ++q)
            av[q] = arow[blk4 * 128 + q * 32 + lane];
#pragma unroll
        for (int q = 0; q < 4; ++q) {
            int blk = blk4 * 4 + q;
            int j0  = blk * 128 + lane * 4;
            float4 bz = __ldg((const float4*)(g_Bz + j0));
            float4 cz = __ldg((const float4*)(g_Cz + j0));

            unsigned nib = (av[q].x > 0) | ((av[q].y > 0) << 1) |
                           ((av[q].z > 0) << 2) | ((av[q].w > 0) << 3);
            unsigned v = nib;
            v |= __shfl_down_sync(0xffffffffu, v, 1) << 4;
            v |= __shfl_down_sync(0xffffffffu, v, 2) << 8;
            v |= __shfl_down_sync(0xffffffffu, v, 4) << 16;
            if ((lane & 7) == 0)
                mrow[blk * 4 + (lane >> 3)] = v;

            float ba[4] = {bz.x, bz.y, bz.z, bz.w};
            float ca[4] = {cz.x, cz.y, cz.z, cz.w};
#pragma unroll
            for (int u = 0; u < 4; ++u) {
                float vv  = fmaxf(ea * ba[u], eb * ca[u]);
                bool  bit = (nib >> u) & 1u;
                float val = bit ? vv : 0.f;
                s  += val;
                vm  = fmaxf(vm, val);
                cnt += (bit && vv > 0.f) ? 1 : 0;
            }
        }
    }
#pragma unroll
    for (int o = 16; o > 0; o >>= 1) {
        s   += __shfl_xor_sync(0xffffffffu, s, o);
        vm   = fmaxf(vm, __shfl_xor_sync(0xffffffffu, vm, o));
        cnt += __shfl_xor_sync(0xffffffffu, cnt, o);
    }
    if (lane == 0) {
        bool active = (vm > THR * s);
        float eaF = 0.f, ebF = 0.f, T3 = CUDART_INF_F;
        if (active) {
            float F = (float)cnt / s;
            eaF = ea * F;
            ebF = eb * F;
            T3  = THR * (float)cnt;
        }
        g_rowc[row] = make_float4(eaF, ebF, T3, 0.f);
    }
}

// ---------------- K3: warp-specialized producer/consumer MMA kernel ---------
// warps 0-3: consumers (all MMAs, 64m x 32n each)
// warps 4-7: producers (weight gen + cp.async B loads)
__global__ void __launch_bounds__(256, 2) k_agg() {
    extern __shared__ __align__(16) char sm[];
    __shared__ unsigned s_u;
    uint32_t smb = smem_u32(sm);

    int tid  = threadIdx.x;
    int lane = tid & 31;
    int wid  = tid >> 5;
    bool producer = (wid >= 4);
    int ptid = tid - 128;         // producer-local tid (0..127)

    float* s_bz = (float*)(sm + SM_TAB);
    float* s_cz = s_bz + JR;

    // producer gen assignment: row gi, 16-j half of BK=32
    int gi  = ptid >> 1;          // 0..63
    int j16 = (ptid & 1) << 4;    // 0 or 16
    // consumer tile: 64m x 32n per warp
    int wn = wid * 32;            // valid for wid 0..3

    while (true) {
        if (tid == 0) s_u = atomicAdd(&g_ctr, 1u);
        __syncthreads();
        unsigned u = s_u;
        if (u >= NUNITS) break;

        int split  = u >> 7;
        int iblk   = u & 127;
        int ib     = iblk * MB;
        int jstart = split * JR;

        float4 rc = make_float4(0.f, 0.f, 0.f, 0.f);
        const unsigned* mrow = nullptr;
        if (producer) {
            rc   = g_rowc[ib + gi];
            mrow = g_mask + (size_t)(ib + gi) * (N / 32) + (jstart >> 5);
        }

        float acc[4][4][4];
#pragma unroll
        for (int mf = 0; mf < 4; ++mf)
#pragma unroll
            for (int nf = 0; nf < 4; ++nf)
#pragma unroll
                for (int q = 0; q < 4; ++q) acc[mf][nf][q] = 0.f;

        auto loadB = [&](int t) {      // producers only: 4 cpa16 each
            int b  = t & 1;
            int jb = jstart + t * BK;
            uint32_t Bh = smb + b * BUF_BYTES + A_BYTES;
#pragma unroll
            for (int q = 0; q < 4; ++q) {
                int idx = ptid + q * 128;
                int r = idx >> 4, g = idx & 15;
                uint32_t doff = (uint32_t)(r * BPITCH + g * 8) * 2;
                cpa16(Bh + doff, g_hh + (size_t)(jb + r) * D + g * 8);
            }
            CPA_COMMIT();
        };

        auto gen_store = [&](int t) {  // producers only: 16 weights each
            int b = t & 1;
            char* Ah = sm + b * BUF_BYTES;
            unsigned mw = __ldg(&mrow[t]) >> j16;
            int lj = t * BK + j16;
            const float4* tb = (const float4*)(s_bz + lj);
            const float4* tc = (const float4*)(s_cz + lj);
            uint32_t* a32 = (uint32_t*)Ah + gi * (APITCH / 2) + (j16 >> 1);
#pragma unroll
            for (int e = 0; e < 4; ++e) {
                float4 bz = tb[e];
                float4 cz = tc[e];
                float ba[4] = {bz.x, bz.y, bz.z, bz.w};
                float ca[4] = {cz.x, cz.y, cz.z, cz.w};
                float w[4];
#pragma unroll
                for (int k = 0; k < 4; ++k) {
                    float v  = fmaxf(rc.x * ba[k], rc.y * ca[k]);
                    bool  ok = (v >= rc.z) && ((mw >> (e * 4 + k)) & 1u);
                    w[k] = ok ? v : 0.f;
                }
                uint32_t p0, p1;
                asm("cvt.rn.f16x2.f32 %0, %1, %2;" : "=r"(p0) : "f"(w[1]), "f"(w[0]));
                asm("cvt.rn.f16x2.f32 %0, %1, %2;" : "=r"(p1) : "f"(w[3]), "f"(w[2]));
                *(uint2*)&a32[e * 2] = make_uint2(p0, p1);
            }
        };

        auto domma = [&](int t) {      // consumers only: 32 MMAs
            int b = t & 1;
            uint32_t Ah = smb + b * BUF_BYTES;
            uint32_t Bh = Ah + A_BYTES;
#pragma unroll
            for (int ks = 0; ks < 2; ++ks) {
                int k0 = ks * 16;
                uint32_t af[4][4];
#pragma unroll
                for (int mf = 0; mf < 4; ++mf) {
                    uint32_t row = mf * 16 + (lane & 15);
                    uint32_t off = row * (APITCH * 2) + (k0 + ((lane >> 4) << 3)) * 2;
                    ldsm4(af[mf], Ah + off);
                }
#pragma unroll
                for (int nf2 = 0; nf2 < 2; ++nf2) {
                    int n0 = wn + nf2 * 16;
                    uint32_t r = k0 + (lane & 7) + ((lane >> 3) & 1) * 8;
                    uint32_t c = n0 + ((lane >> 4) << 3);
                    uint32_t off = r * (BPITCH * 2) + c * 2;
                    uint32_t bh[4];
                    ldsm4t(bh, Bh + off);
#pragma unroll
                    for (int mf = 0; mf < 4; ++mf) {
                        mma16816(acc[mf][nf2 * 2],     af[mf], bh);
                        mma16816(acc[mf][nf2 * 2 + 1], af[mf], bh + 2);
                    }
                }
            }
        };

        // ---- unit prologue: tables + B(0), then A(0) -------------------------
        if (producer) loadB(0);
        if (tid < 128)
            ((float4*)s_bz)[tid] = __ldg((const float4*)(g_Bz + jstart) + tid);
        else
            ((float4*)s_cz)[tid - 128] =
                __ldg((const float4*)(g_Cz + jstart) + (tid - 128));
        __syncthreads();               // tables ready
        if (producer) gen_store(0);

        // ---- pipeline: consumers mma(t) overlap producers gen(t+1)+loadB(t+1)
        for (int t = 0; t < NT; ++t) {
            if (producer) CPA_WAIT0(); // B(t) copies done (issued at t-1)
            __syncthreads();           // A(t)+B(t) visible; buffer t-1 reads fenced
            if (producer) {
                if (t + 1 < NT) {
                    loadB(t + 1);
                    gen_store(t + 1);
                }
            } else {
                domma(t);
            }
        }

        // ---- epilogue: consumers write split partial -------------------------
        if (!producer) {
            int r0    = ib + (lane >> 2);
            int cbase = wn + (lane & 3) * 2;
#pragma unroll
            for (int mf = 0; mf < 4; ++mf)
#pragma unroll
                for (int nf = 0; nf < 4; ++nf) {
                    int row = r0 + mf * 16;
                    int col = cbase + nf * 8;
                    float* p = &g_part[split][(size_t)row * D + col];
                    *(float2*)p           = make_float2(acc[mf][nf][0], acc[mf][nf][1]);
                    *(float2*)(p + 8 * D) = make_float2(acc[mf][nf][2], acc[mf][nf][3]);
                }
        }
    }
}

// ---------------- K4: combine partials + residual + ELU ---------------------
__global__ void k_out(float* __restrict__ out) {
    int g = blockIdx.x * blockDim.x + threadIdx.x;
    float4 v = ((const float4*)g_h)[g];
#pragma unroll
    for (int s = 0; s < SPLIT; ++s) {
        float4 p = __ldg((const float4*)g_part[s] + g);
        v.x += p.x; v.y += p.y; v.z += p.z; v.w += p.w;
    }
    float4 o;
    o.x = (v.x > 0.f) ? v.x : expm1f(v.x);
    o.y = (v.y > 0.f) ? v.y : expm1f(v.y);
    o.z = (v.z > 0.f) ? v.z : expm1f(v.z);
    o.w = (v.w > 0.f) ? v.w : expm1f(v.w);
    ((float4*)out)[g] = o;
}

// ---------------- launch ----------------------------------------------------
extern "C" void kernel_launch(void* const* d_in, const int* in_sizes, int n_in,
                              void* d_out, int out_size) {
    (void)in_sizes; (void)n_in; (void)out_size;
    const float* x   = (const float*)d_in[0];
    const float* W   = (const float*)d_in[1];
    const float* a   = (const float*)d_in[2];
    const int*   adj = (const int*)d_in[3];
    float*       out = (float*)d_out;

    cudaFuncSetAttribute(k_agg, cudaFuncAttributeMaxDynamicSharedMemorySize, SMEM_DYN);

    k_h    <<<N, 128>>>(x, W, a);
    k_stats<<<N / SROWS, 256>>>(adj);
    k_agg  <<<NCTA, 256, SMEM_DYN>>>();
    k_out  <<<(N * D) / 1024, 256>>>(out);
}